// round 1
// baseline (speedup 1.0000x reference)
#include <cuda_runtime.h>
#include <cuda_bf16.h>
#include <cstdint>

// Problem constants
#define NB   32      // batch
#define NC   8192    // checks
#define NV   16384   // vars
#define NITR 15
#define RCAP 64      // max check degree (mean ~16.4)
#define CCAP 40      // max var degree (mean ~8.2)

// Scratch (allocation-free: __device__ globals)
__device__ int   g_csr_col[NC * RCAP];
__device__ int   g_csr_cnt[NC];
__device__ int   g_csc_row[NV * CCAP];
__device__ int   g_csc_cnt[NV];
__device__ float g_vbel[NV * NB];    // beliefs, transposed (v, b)
__device__ float g_cmsg[NC * NB];    // check messages, transposed (c, b)
__device__ float g_llr_t[NV * NB];   // channel llrs, transposed
__device__ float g_ssign[NC * NB];   // 1 - 2*syndrome, transposed

// ---------------------------------------------------------------------------
__global__ void zero_cnt_kernel() {
    int tid = blockIdx.x * blockDim.x + threadIdx.x;
    if (tid < NC) g_csr_cnt[tid] = 0;
    if (tid < NV) g_csc_cnt[tid] = 0;
}

// One warp per H row; lanes stride over the row with 16B vector loads.
__global__ void extract_kernel(const uint4* __restrict__ H) {
    int warp = (blockIdx.x * blockDim.x + threadIdx.x) >> 5;
    if (warp >= NC) return;
    int lane = threadIdx.x & 31;
    const uint4* row = H + (size_t)warp * (NV / 4);

    #pragma unroll 4
    for (int i = lane; i < NV / 4; i += 32) {
        uint4 u = row[i];
        if (u.x | u.y | u.z | u.w) {
            int base = i * 4;
            #pragma unroll
            for (int j = 0; j < 4; j++) {
                unsigned val = (j == 0) ? u.x : (j == 1) ? u.y : (j == 2) ? u.z : u.w;
                if (val) {
                    int v = base + j;
                    int p = atomicAdd(&g_csr_cnt[warp], 1);
                    if (p < RCAP) g_csr_col[warp * RCAP + p] = v;
                    int q = atomicAdd(&g_csc_cnt[v], 1);
                    if (q < CCAP) g_csc_row[v * CCAP + q] = warp;
                }
            }
        }
    }
}

// Transpose llrs (B,V)->(V,B), init beliefs; transpose syndrome sign (B,C)->(C,B)
__global__ void prep_kernel(const float* __restrict__ syndrome,
                            const float* __restrict__ llr) {
    int tid = blockIdx.x * blockDim.x + threadIdx.x;
    if (tid < NV * NB) {
        int v = tid >> 5, b = tid & 31;
        float x = llr[b * NV + v];
        g_llr_t[tid] = x;
        g_vbel[tid]  = x;
    }
    int tid2 = tid - NV * NB;
    if (tid2 >= 0 && tid2 < NC * NB) {
        int c = tid2 >> 5, b = tid2 & 31;
        g_ssign[tid2] = 1.0f - 2.0f * syndrome[b * NC + c];
    }
}

// v -> c : one warp per check, lane = batch element
__global__ void check_kernel(const float* __restrict__ w_vc) {
    int c = (blockIdx.x * blockDim.x + threadIdx.x) >> 5;
    if (c >= NC) return;
    int lane = threadIdx.x & 31;
    int deg = g_csr_cnt[c];
    if (deg > RCAP) deg = RCAP;
    const int* cols = &g_csr_col[c * RCAP];

    float sum = 0.0f;
    int k = 0;
    for (; k + 4 <= deg; k += 4) {
        int c0 = cols[k], c1 = cols[k + 1], c2 = cols[k + 2], c3 = cols[k + 3];
        float a = g_vbel[c0 * NB + lane];
        float b = g_vbel[c1 * NB + lane];
        float d = g_vbel[c2 * NB + lane];
        float e = g_vbel[c3 * NB + lane];
        sum += (a + b) + (d + e);
    }
    for (; k < deg; k++) sum += g_vbel[cols[k] * NB + lane];

    float t = tanhf(0.5f * (*w_vc) * sum);
    g_cmsg[c * NB + lane] = g_ssign[c * NB + lane] * t;
}

// c -> v + damped update : one warp per var, lane = batch element
__global__ void var_kernel(const float* __restrict__ w_cv,
                           const float* __restrict__ damping) {
    int v = (blockIdx.x * blockDim.x + threadIdx.x) >> 5;
    if (v >= NV) return;
    int lane = threadIdx.x & 31;
    int deg = g_csc_cnt[v];
    if (deg > CCAP) deg = CCAP;
    const int* rows = &g_csc_row[v * CCAP];

    float sum = 0.0f;
    int k = 0;
    for (; k + 4 <= deg; k += 4) {
        int r0 = rows[k], r1 = rows[k + 1], r2 = rows[k + 2], r3 = rows[k + 3];
        float a = g_cmsg[r0 * NB + lane];
        float b = g_cmsg[r1 * NB + lane];
        float d = g_cmsg[r2 * NB + lane];
        float e = g_cmsg[r3 * NB + lane];
        sum += (a + b) + (d + e);
    }
    for (; k < deg; k++) sum += g_cmsg[rows[k] * NB + lane];

    float dmp = *damping;
    float wc  = *w_cv;
    int idx = v * NB + lane;
    float old = g_vbel[idx];
    g_vbel[idx] = dmp * old + (1.0f - dmp) * (g_llr_t[idx] + wc * sum);
}

// out[b][v] = sigmoid(-belief) = 1/(1+exp(belief))
__global__ void output_kernel(float* __restrict__ out) {
    int tid = blockIdx.x * blockDim.x + threadIdx.x;
    if (tid >= NB * NV) return;
    int b = tid / NV, v = tid % NV;
    float x = g_vbel[v * NB + b];
    out[tid] = 1.0f / (1.0f + expf(x));
}

// ---------------------------------------------------------------------------
extern "C" void kernel_launch(void* const* d_in, const int* in_sizes, int n_in,
                              void* d_out, int out_size) {
    const float* syndrome = (const float*)d_in[0];   // (32, 8192)
    const uint4* parity   = (const uint4*)d_in[1];   // (8192, 16384) fp32 as bits
    const float* llr      = (const float*)d_in[2];   // (32, 16384)
    const float* w_vc     = (const float*)d_in[3];
    const float* w_cv     = (const float*)d_in[4];
    const float* damping  = (const float*)d_in[5];
    float* out = (float*)d_out;

    zero_cnt_kernel<<<(NV + 255) / 256, 256>>>();
    extract_kernel<<<(NC * 32 + 255) / 256, 256>>>(parity);

    int prep_threads = NV * NB + NC * NB;
    prep_kernel<<<(prep_threads + 255) / 256, 256>>>(syndrome, llr);

    for (int it = 0; it < NITR; it++) {
        check_kernel<<<(NC * 32 + 255) / 256, 256>>>(w_vc);
        var_kernel<<<(NV * 32 + 255) / 256, 256>>>(w_cv, damping);
    }

    output_kernel<<<(NB * NV + 255) / 256, 256>>>(out);
}

// round 2
// speedup vs baseline: 1.0961x; 1.0961x over previous
#include <cuda_runtime.h>
#include <cuda_bf16.h>
#include <cstdint>

// Problem constants
#define NB   32      // batch
#define NC   8192    // checks
#define NV   16384   // vars
#define NITR 15
#define RCAP 64      // max check degree (mean ~16.4, padded to mult of 8)
#define CCAP 40      // max var degree (mean ~8.2, padded to mult of 8)

// Scratch (allocation-free: __device__ globals)
__device__ int   g_csr_col[NC * RCAP];
__device__ int   g_csr_cnt[NC];
__device__ int   g_csc_row[NV * CCAP];
__device__ int   g_csc_cnt[NV];
__device__ float g_vbel[(NV + 1) * NB];   // beliefs (v, b); row NV = zeros (pad target)
__device__ float g_cmsg[(NC + 1) * NB];   // check msgs (c, b); row NC = zeros (pad target)
__device__ float g_llr_t[NV * NB];        // channel llrs, transposed
__device__ float g_ssign[NC * NB];        // 1 - 2*syndrome, transposed

// ---------------------------------------------------------------------------
__global__ void zero_cnt_kernel() {
    int tid = blockIdx.x * blockDim.x + threadIdx.x;
    if (tid < NC) g_csr_cnt[tid] = 0;
    if (tid < NV) g_csc_cnt[tid] = 0;
}

// One warp per H row; lanes stride over the row with 16B vector loads.
__global__ void extract_kernel(const uint4* __restrict__ H) {
    int warp = (blockIdx.x * blockDim.x + threadIdx.x) >> 5;
    if (warp >= NC) return;
    int lane = threadIdx.x & 31;
    const uint4* row = H + (size_t)warp * (NV / 4);

    #pragma unroll 4
    for (int i = lane; i < NV / 4; i += 32) {
        uint4 u = row[i];
        if (u.x | u.y | u.z | u.w) {
            int base = i * 4;
            #pragma unroll
            for (int j = 0; j < 4; j++) {
                unsigned val = (j == 0) ? u.x : (j == 1) ? u.y : (j == 2) ? u.z : u.w;
                if (val) {
                    int v = base + j;
                    int p = atomicAdd(&g_csr_cnt[warp], 1);
                    if (p < RCAP) g_csr_col[warp * RCAP + p] = v;
                    int q = atomicAdd(&g_csc_cnt[v], 1);
                    if (q < CCAP) g_csc_row[v * CCAP + q] = warp;
                }
            }
        }
    }
}

// Pad adjacency lists to a multiple of 8 with dummy indices (NV / NC) whose
// message rows are permanently zero — makes gather loops fixed-shape so
// ptxas front-batches the loads (MLP >= 8).
__global__ void pad_kernel() {
    int tid = blockIdx.x * blockDim.x + threadIdx.x;
    if (tid < NC) {
        int cnt = g_csr_cnt[tid]; if (cnt > RCAP) cnt = RCAP;
        int p = (cnt + 7) & ~7;   if (p > RCAP) p = RCAP;
        for (int k = cnt; k < p; k++) g_csr_col[tid * RCAP + k] = NV;
        g_csr_cnt[tid] = p;
    }
    if (tid < NV) {
        int cnt = g_csc_cnt[tid]; if (cnt > CCAP) cnt = CCAP;
        int p = (cnt + 7) & ~7;   if (p > CCAP) p = CCAP;
        for (int k = cnt; k < p; k++) g_csc_row[tid * CCAP + k] = NC;
        g_csc_cnt[tid] = p;
    }
}

// Transpose llrs (B,V)->(V,B), init beliefs; transpose syndrome sign (B,C)->(C,B);
// zero the dummy pad rows.
__global__ void prep_kernel(const float* __restrict__ syndrome,
                            const float* __restrict__ llr) {
    int tid = blockIdx.x * blockDim.x + threadIdx.x;
    if (tid < NV * NB) {
        int v = tid >> 5, b = tid & 31;
        float x = llr[b * NV + v];
        g_llr_t[tid] = x;
        g_vbel[tid]  = x;
    }
    int tid2 = tid - NV * NB;
    if (tid2 >= 0 && tid2 < NC * NB) {
        int c = tid2 >> 5, b = tid2 & 31;
        g_ssign[tid2] = 1.0f - 2.0f * syndrome[b * NC + c];
    }
    if (tid < NB) {
        g_vbel[NV * NB + tid] = 0.0f;   // dummy var row
        g_cmsg[NC * NB + tid] = 0.0f;   // dummy check row
    }
}

// v -> c : one warp per check, lane = batch element. Fixed 8-wide chunks.
__global__ void check_kernel(const float* __restrict__ w_vc) {
    int c = (blockIdx.x * blockDim.x + threadIdx.x) >> 5;
    if (c >= NC) return;
    int lane = threadIdx.x & 31;
    int degp = g_csr_cnt[c];                 // multiple of 8
    const int4* cols = (const int4*)&g_csr_col[c * RCAP];
    float wv = *w_vc;

    float sum = 0.0f;
    for (int k = 0; k < degp; k += 8) {
        int4 i0 = cols[(k >> 2)];
        int4 i1 = cols[(k >> 2) + 1];
        int idx[8] = { i0.x, i0.y, i0.z, i0.w, i1.x, i1.y, i1.z, i1.w };
        float x[8];
        #pragma unroll
        for (int j = 0; j < 8; j++) x[j] = g_vbel[idx[j] * NB + lane];
        #pragma unroll
        for (int j = 0; j < 8; j++) sum += x[j];
    }

    float t = tanhf(0.5f * wv * sum);
    g_cmsg[c * NB + lane] = g_ssign[c * NB + lane] * t;
}

// c -> v + damped update : one warp per var, lane = batch element.
__global__ void var_kernel(const float* __restrict__ w_cv,
                           const float* __restrict__ damping) {
    int v = (blockIdx.x * blockDim.x + threadIdx.x) >> 5;
    if (v >= NV) return;
    int lane = threadIdx.x & 31;
    int degp = g_csc_cnt[v];                 // multiple of 8
    const int4* rows = (const int4*)&g_csc_row[v * CCAP];

    float sum = 0.0f;
    for (int k = 0; k < degp; k += 8) {
        int4 i0 = rows[(k >> 2)];
        int4 i1 = rows[(k >> 2) + 1];
        int idx[8] = { i0.x, i0.y, i0.z, i0.w, i1.x, i1.y, i1.z, i1.w };
        float x[8];
        #pragma unroll
        for (int j = 0; j < 8; j++) x[j] = g_cmsg[idx[j] * NB + lane];
        #pragma unroll
        for (int j = 0; j < 8; j++) sum += x[j];
    }

    float dmp = *damping;
    float wc  = *w_cv;
    int idx = v * NB + lane;
    float old = g_vbel[idx];
    g_vbel[idx] = dmp * old + (1.0f - dmp) * (g_llr_t[idx] + wc * sum);
}

// out[b][v] = sigmoid(-belief) = 1/(1+exp(belief))
__global__ void output_kernel(float* __restrict__ out) {
    int tid = blockIdx.x * blockDim.x + threadIdx.x;
    if (tid >= NB * NV) return;
    int b = tid / NV, v = tid % NV;
    float x = g_vbel[v * NB + b];
    out[tid] = 1.0f / (1.0f + expf(x));
}

// ---------------------------------------------------------------------------
extern "C" void kernel_launch(void* const* d_in, const int* in_sizes, int n_in,
                              void* d_out, int out_size) {
    const float* syndrome = (const float*)d_in[0];   // (32, 8192)
    const uint4* parity   = (const uint4*)d_in[1];   // (8192, 16384) fp32 as bits
    const float* llr      = (const float*)d_in[2];   // (32, 16384)
    const float* w_vc     = (const float*)d_in[3];
    const float* w_cv     = (const float*)d_in[4];
    const float* damping  = (const float*)d_in[5];
    float* out = (float*)d_out;

    zero_cnt_kernel<<<(NV + 255) / 256, 256>>>();
    extract_kernel<<<(NC * 32 + 255) / 256, 256>>>(parity);
    pad_kernel<<<(NV + 255) / 256, 256>>>();

    int prep_threads = NV * NB + NC * NB;
    prep_kernel<<<(prep_threads + 255) / 256, 256>>>(syndrome, llr);

    for (int it = 0; it < NITR; it++) {
        check_kernel<<<(NC * 32 + 255) / 256, 256>>>(w_vc);
        var_kernel<<<(NV * 32 + 255) / 256, 256>>>(w_cv, damping);
    }

    output_kernel<<<(NB * NV + 255) / 256, 256>>>(out);
}

// round 3
// speedup vs baseline: 1.1239x; 1.0254x over previous
#include <cuda_runtime.h>
#include <cuda_bf16.h>
#include <cstdint>

// Problem constants
#define NB   32      // batch
#define NC   8192    // checks
#define NV   16384   // vars
#define NITR 15
#define RCAP 64      // max check degree slots (mean ~16.4), tiers of 16
#define CCAP 40      // max var degree slots (mean ~8.2), tiers of 8

// Scratch (allocation-free: __device__ globals)
// Adjacency lists store PRE-SCALED indices (idx * NB). Dummy = zero row.
__device__ int   g_csr_col[NC * RCAP];
__device__ int   g_csr_cnt[NC];
__device__ int   g_csc_row[NV * CCAP];
__device__ int   g_csc_cnt[NV];
__device__ float g_vbel[(NV + 1) * NB];   // beliefs (v, b); row NV = zeros
__device__ float g_cmsg[(NC + 1) * NB];   // check msgs (c, b); row NC = zeros
__device__ float g_llr_t[NV * NB];        // channel llrs, transposed
__device__ float g_ssign[NC * NB];        // 1 - 2*syndrome, transposed

// ---------------------------------------------------------------------------
__global__ void zero_cnt_kernel() {
    int tid = blockIdx.x * blockDim.x + threadIdx.x;
    if (tid < NC) g_csr_cnt[tid] = 0;
    if (tid < NV) g_csc_cnt[tid] = 0;
    if (tid < NB) {
        g_vbel[NV * NB + tid] = 0.0f;   // dummy var row
        g_cmsg[NC * NB + tid] = 0.0f;   // dummy check row
    }
}

// One warp per H row; lanes stride over the row with 16B vector loads.
__global__ void extract_kernel(const uint4* __restrict__ H) {
    int warp = (blockIdx.x * blockDim.x + threadIdx.x) >> 5;
    if (warp >= NC) return;
    int lane = threadIdx.x & 31;
    const uint4* row = H + (size_t)warp * (NV / 4);

    #pragma unroll 4
    for (int i = lane; i < NV / 4; i += 32) {
        uint4 u = row[i];
        if (u.x | u.y | u.z | u.w) {
            int base = i * 4;
            #pragma unroll
            for (int j = 0; j < 4; j++) {
                unsigned val = (j == 0) ? u.x : (j == 1) ? u.y : (j == 2) ? u.z : u.w;
                if (val) {
                    int v = base + j;
                    int p = atomicAdd(&g_csr_cnt[warp], 1);
                    if (p < RCAP) g_csr_col[warp * RCAP + p] = v * NB;       // pre-scaled
                    int q = atomicAdd(&g_csc_cnt[v], 1);
                    if (q < CCAP) g_csc_row[v * CCAP + q] = warp * NB;       // pre-scaled
                }
            }
        }
    }
}

// Pad adjacency lists to tier boundaries with dummy (zero-row) scaled indices.
// Checks: multiple of 16 (tiers 16/32/48/64). Vars: multiple of 8 (8..40).
__global__ void pad_kernel() {
    int tid = blockIdx.x * blockDim.x + threadIdx.x;
    if (tid < NC) {
        int cnt = g_csr_cnt[tid]; if (cnt > RCAP) cnt = RCAP;
        int p = (cnt + 15) & ~15; if (p > RCAP) p = RCAP;
        if (p == 0) p = 16;
        for (int k = cnt; k < p; k++) g_csr_col[tid * RCAP + k] = NV * NB;
        g_csr_cnt[tid] = p;
    }
    if (tid < NV) {
        int cnt = g_csc_cnt[tid]; if (cnt > CCAP) cnt = CCAP;
        int p = (cnt + 7) & ~7;   if (p > CCAP) p = CCAP;
        if (p == 0) p = 8;
        for (int k = cnt; k < p; k++) g_csc_row[tid * CCAP + k] = NC * NB;
        g_csc_cnt[tid] = p;
    }
}

// Coalesced smem-tile transposes:
// blocks [0, NV/32)            : llr (B,V)->(V,B) + vbel init
// blocks [NV/32, NV/32+NC/32)  : syndrome sign (B,C)->(C,B)
__global__ void prep_kernel(const float* __restrict__ syndrome,
                            const float* __restrict__ llr) {
    __shared__ float tile[32][33];
    int tx = threadIdx.x & 31, ty = threadIdx.x >> 5;   // 256 thr: ty in 0..7
    int bid = blockIdx.x;
    if (bid < NV / 32) {
        int v0 = bid * 32;
        #pragma unroll
        for (int i = 0; i < 32; i += 8)
            tile[ty + i][tx] = llr[(size_t)(ty + i) * NV + v0 + tx];
        __syncthreads();
        #pragma unroll
        for (int i = 0; i < 32; i += 8) {
            float x = tile[tx][ty + i];
            int idx = (v0 + ty + i) * NB + tx;
            g_llr_t[idx] = x;
            g_vbel[idx]  = x;
        }
    } else {
        int c0 = (bid - NV / 32) * 32;
        #pragma unroll
        for (int i = 0; i < 32; i += 8)
            tile[ty + i][tx] = syndrome[(size_t)(ty + i) * NC + c0 + tx];
        __syncthreads();
        #pragma unroll
        for (int i = 0; i < 32; i += 8)
            g_ssign[(c0 + ty + i) * NB + tx] = 1.0f - 2.0f * tile[tx][ty + i];
    }
}

// Straight-line gather+sum over N4*4 pre-scaled indices: all index loads
// front-batched, then all gathers front-batched -> ~2 L2 round trips total.
template <int N4>
__device__ __forceinline__ float gather_sum(const int4* __restrict__ p,
                                            const float* __restrict__ tbl,
                                            int lane) {
    int4 q[N4];
    #pragma unroll
    for (int i = 0; i < N4; i++) q[i] = p[i];
    float x[N4 * 4];
    #pragma unroll
    for (int i = 0; i < N4; i++) {
        x[4 * i + 0] = tbl[q[i].x + lane];
        x[4 * i + 1] = tbl[q[i].y + lane];
        x[4 * i + 2] = tbl[q[i].z + lane];
        x[4 * i + 3] = tbl[q[i].w + lane];
    }
    float s = 0.0f;
    #pragma unroll
    for (int i = 0; i < N4 * 4; i++) s += x[i];
    return s;
}

// v -> c : one warp per check, lane = batch element.
__global__ void check_kernel(const float* __restrict__ w_vc) {
    int c = (blockIdx.x * blockDim.x + threadIdx.x) >> 5;
    if (c >= NC) return;
    int lane = threadIdx.x & 31;
    int degp = g_csr_cnt[c];                       // 16/32/48/64
    const int4* cols = (const int4*)&g_csr_col[c * RCAP];

    float sum;
    if (degp == 16)      sum = gather_sum<4>(cols, g_vbel, lane);
    else if (degp == 32) sum = gather_sum<8>(cols, g_vbel, lane);
    else {                                          // rare tail (48/64)
        sum = 0.0f;
        for (int k = 0; k < degp; k += 16)
            sum += gather_sum<4>(cols + (k >> 2), g_vbel, lane);
    }

    float t = tanhf(0.5f * (*w_vc) * sum);
    g_cmsg[c * NB + lane] = g_ssign[c * NB + lane] * t;
}

// c -> v + damped update : one warp per var, lane = batch element.
__global__ void var_kernel(const float* __restrict__ w_cv,
                           const float* __restrict__ damping) {
    int v = (blockIdx.x * blockDim.x + threadIdx.x) >> 5;
    if (v >= NV) return;
    int lane = threadIdx.x & 31;
    int degp = g_csc_cnt[v];                       // 8/16/24/32/40
    const int4* rows = (const int4*)&g_csc_row[v * CCAP];

    float sum;
    if (degp == 8)       sum = gather_sum<2>(rows, g_cmsg, lane);
    else if (degp == 16) sum = gather_sum<4>(rows, g_cmsg, lane);
    else {                                          // rare tail (24+)
        sum = 0.0f;
        for (int k = 0; k < degp; k += 8)
            sum += gather_sum<2>(rows + (k >> 2), g_cmsg, lane);
    }

    float dmp = *damping;
    int idx = v * NB + lane;
    float old = g_vbel[idx];
    g_vbel[idx] = dmp * old + (1.0f - dmp) * (g_llr_t[idx] + (*w_cv) * sum);
}

// out[b][v] = sigmoid(-belief); smem-tile transpose, coalesced both sides.
__global__ void output_kernel(float* __restrict__ out) {
    __shared__ float tile[32][33];
    int tx = threadIdx.x & 31, ty = threadIdx.x >> 5;
    int v0 = blockIdx.x * 32;
    #pragma unroll
    for (int i = 0; i < 32; i += 8)
        tile[ty + i][tx] = g_vbel[(v0 + ty + i) * NB + tx];
    __syncthreads();
    #pragma unroll
    for (int i = 0; i < 32; i += 8) {
        float x = tile[tx][ty + i];
        out[(size_t)(ty + i) * NV + v0 + tx] = 1.0f / (1.0f + expf(x));
    }
}

// ---------------------------------------------------------------------------
extern "C" void kernel_launch(void* const* d_in, const int* in_sizes, int n_in,
                              void* d_out, int out_size) {
    const float* syndrome = (const float*)d_in[0];   // (32, 8192)
    const uint4* parity   = (const uint4*)d_in[1];   // (8192, 16384) fp32 as bits
    const float* llr      = (const float*)d_in[2];   // (32, 16384)
    const float* w_vc     = (const float*)d_in[3];
    const float* w_cv     = (const float*)d_in[4];
    const float* damping  = (const float*)d_in[5];
    float* out = (float*)d_out;

    zero_cnt_kernel<<<(NV + 255) / 256, 256>>>();
    extract_kernel<<<(NC * 32 + 255) / 256, 256>>>(parity);
    pad_kernel<<<(NV + 255) / 256, 256>>>();
    prep_kernel<<<(NV / 32 + NC / 32), 256>>>(syndrome, llr);

    for (int it = 0; it < NITR; it++) {
        check_kernel<<<(NC * 32 + 255) / 256, 256>>>(w_vc);
        var_kernel<<<(NV * 32 + 255) / 256, 256>>>(w_cv, damping);
    }

    output_kernel<<<NV / 32, 256>>>(out);
}